// round 16
// baseline (speedup 1.0000x reference)
#include <cuda_runtime.h>
#include <cstdint>

#define A_STRIDE 132                     // words
#define B_STRIDE 264                     // words
#define KCHUNK 16
#define NCHUNK 8
#define A_WORDS (64 * A_STRIDE)          // 8448 (64-row half tile)
#define B_WORDS (KCHUNK * B_STRIDE)      // 4224
#define SMEM_BYTES ((A_WORDS + 4 * B_WORDS) * 4)   // 101376 -> 2 CTAs/SM

static __device__ __forceinline__ uint32_t tf32u(float x) {
    uint32_t r;
    asm("cvt.rna.tf32.f32 %0, %1;" : "=r"(r) : "f"(x));
    return r;
}
static __device__ __forceinline__ void cp16(uint32_t dst, const void* src) {
    asm volatile("cp.async.cg.shared.global [%0], [%1], 16;" :: "r"(dst), "l"(src));
}
#define CP_COMMIT() asm volatile("cp.async.commit_group;" ::: "memory")
#define CP_WAIT(n)  asm volatile("cp.async.wait_group %0;" :: "n"(n) : "memory")

static __device__ __forceinline__ void pf_l2(const void* p) {
    asm volatile("prefetch.global.L2 [%0];" :: "l"(p));
}
// fire-and-forget L2-side float add (no return latency)
static __device__ __forceinline__ void red2_f32(float* p, float2 v) {
    asm volatile("red.global.add.f32 [%0], %1;"   :: "l"(p), "f"(v.x) : "memory");
    asm volatile("red.global.add.f32 [%0+4], %1;" :: "l"(p), "f"(v.y) : "memory");
}
static __device__ __forceinline__ void ldsm_x4(uint32_t r[4], uint32_t addr) {
    asm volatile("ldmatrix.sync.aligned.m8n8.x4.shared.b16 {%0,%1,%2,%3}, [%4];"
                 : "=r"(r[0]), "=r"(r[1]), "=r"(r[2]), "=r"(r[3]) : "r"(addr));
}
static __device__ __forceinline__ void mma_tf32(float c[4], const uint32_t a[4],
                                                uint32_t b0, uint32_t b1) {
    asm volatile(
        "mma.sync.aligned.m16n8k8.row.col.f32.tf32.tf32.f32 "
        "{%0,%1,%2,%3}, {%4,%5,%6,%7}, {%8,%9}, {%0,%1,%2,%3};"
        : "+f"(c[0]), "+f"(c[1]), "+f"(c[2]), "+f"(c[3])
        : "r"(a[0]), "r"(a[1]), "r"(a[2]), "r"(a[3]), "r"(b0), "r"(b1));
}

// ---------------------------------------------------------------------------
// Persistent, 256 thr/CTA, 2 CTAs/SM. Half-tile t -> (mhh=(t&1)*64,
// rc=(t>>1)&127, b=t>>8): D[64,256] = softmax(attn[b,rc,mhh..]+g) @ V_t.
// Warp w owns n-cols [w*32, w*32+32): B slab warp-private; zero block syncs
// in chunk loop.  Cross-tile schedule (per-thread cp.async FIFO):
//   tile head: prefetch.L2 of A(t+1) + V(t+1) (hit-ify next tile's cp.async)
//   c5/c6/c7 issue B(t+1, 0/1/2); post-chunk sync -> issue A(t+1) -> epilogue
//   head: wait(0); chunks: c<=2 none, c3..c7 wait(2); last tile 2/1/0 tail.
// term1 epilogue: plain stores (kept in L2 for term2).
// term2 epilogue: red.global.add (no load latency, half the LTS ops).
// ---------------------------------------------------------------------------
__global__ void __launch_bounds__(256, 2) gt_mma(
    const float* __restrict__ attn, const float* __restrict__ V,
    const float* __restrict__ sp, const float* __restrict__ bp,
    float* __restrict__ out, int term, int ntiles)
{
    extern __shared__ uint32_t smem[];
    uint32_t* As = smem;                         // [64][132] tf32
    uint32_t* Bb = smem + A_WORDS;               // 4-ring of [16][264] raw fp32
    const uint32_t As_u = (uint32_t)__cvta_generic_to_shared(As);
    const uint32_t Bu   = (uint32_t)__cvta_generic_to_shared(Bb);

    const int tid = threadIdx.x, lane = tid & 31, wid = tid >> 5;
    const int nCta = gridDim.x;
    const float sh = sp[0], bi = bp[0];
    const size_t vstride = term ? (size_t)32768 : (size_t)256;

    const int nq = wid * 32;
    const int lr = lane >> 2, lc = lane & 3;
    const int lm_mat = lane >> 3, lm_row = lane & 7;
    const int lm_roff = (lm_mat & 1) * 8 + lm_row;
    const int lm_koff = (lm_mat >> 1) * 4;

    auto voff_of = [&](int t) -> size_t {
        int rc = (t >> 1) & 127, b = t >> 8;
        return term ? ((size_t)b * 4194304 + (size_t)rc * 256)
                    : (((size_t)b * 128 + rc) * (size_t)32768);
    };
    auto issue_A = [&](int t) {
        int mhh = (t & 1) * 64, rc = (t >> 1) & 127, b = t >> 8;
        const float* src = attn + ((size_t)b * 128 + rc) * (size_t)16384
                         + (size_t)mhh * 128;
        #pragma unroll
        for (int q = 0; q < 8; ++q) {
            int c = q * 256 + tid;
            int row = c >> 5, w = c & 31;
            cp16(As_u + (uint32_t)row * (A_STRIDE * 4) + (uint32_t)w * 16,
                 src + row * 128 + w * 4);
        }
        CP_COMMIT();
    };
    auto issue_B = [&](int t, int chunk) {       // warp-private 16k x 32n slab
        const float* src = V + voff_of(t) + (size_t)(chunk * KCHUNK) * vstride + nq;
        const uint32_t dst = Bu + (uint32_t)(chunk & 3) * (B_WORDS * 4)
                           + (uint32_t)nq * 4;
        #pragma unroll
        for (int q = 0; q < 4; ++q) {
            int c = q * 32 + lane;
            int row = c >> 3, g = c & 7;
            cp16(dst + (uint32_t)row * (B_STRIDE * 4) + (uint32_t)g * 16,
                 src + (size_t)row * vstride + g * 4);
        }
        CP_COMMIT();
    };
    auto prefetch_tile = [&](int t) {            // pull A(t)+V(t) into L2
        int mhh = (t & 1) * 64, rc = (t >> 1) & 127, b = t >> 8;
        const float* asrc = attn + ((size_t)b * 128 + rc) * (size_t)16384
                          + (size_t)mhh * 128;
        #pragma unroll
        for (int i = 0; i < 2; ++i)              // 512 x 128B lines (A)
            pf_l2(asrc + (size_t)(i * 256 + tid) * 32);
        const float* vsrc = V + voff_of(t);
        #pragma unroll
        for (int i = 0; i < 4; ++i) {            // 1024 lines (V: 128 rows x 8)
            int idx = i * 256 + tid;
            int row = idx >> 3, lq = idx & 7;
            pf_l2(vsrc + (size_t)row * vstride + lq * 32);
        }
    };

    int t = blockIdx.x;
    if (t >= ntiles) return;

    issue_A(t);
    issue_B(t, 0); issue_B(t, 1); issue_B(t, 2);

    #pragma unroll 1
    for (; t < ntiles; t += nCta) {
        const bool last = (t + nCta >= ntiles);
        const int mhh = (t & 1) * 64;
        const size_t off = voff_of(t) + (size_t)mhh * vstride;

        // pull the NEXT tile's inputs into L2 while this tile computes
        if (!last) prefetch_tile(t + nCta);

        // ---- head: everything for tile t drained (covered by prev epilogue) ----
        CP_WAIT(0);
        __syncthreads();

        // ---- softmax in place (no max pass; exponents bounded) ----
        float* Af = (float*)As;
        #pragma unroll 2
        for (int rr = 0; rr < 8; ++rr) {
            int row = wid * 8 + rr;
            float4 v = *(const float4*)(Af + row * A_STRIDE + lane * 4);
            float fr = (float)(mhh + row);
            float e[4]; float sum = 0.f;
            #pragma unroll
            for (int j = 0; j < 4; ++j) {
                float d = (float)(lane * 4 + j) - fr;
                float vv = (j == 0 ? v.x : j == 1 ? v.y : j == 2 ? v.z : v.w)
                           - fmaf(sh, d * d, bi);
                e[j] = __expf(vv);
                sum += e[j];
            }
            #pragma unroll
            for (int o = 16; o > 0; o >>= 1) sum += __shfl_xor_sync(~0u, sum, o);
            float inv = 1.0f / sum;
            uint4 w = make_uint4(tf32u(e[0] * inv), tf32u(e[1] * inv),
                                 tf32u(e[2] * inv), tf32u(e[3] * inv));
            *(uint4*)(As + row * A_STRIDE + lane * 4) = w;
        }
        __syncthreads();

        float acc[4][4][4];
        #pragma unroll
        for (int u = 0; u < 4; ++u)
            #pragma unroll
            for (int j = 0; j < 4; ++j)
                #pragma unroll
                for (int q = 0; q < 4; ++q) acc[u][j][q] = 0.f;

        // ---- 8 k-chunks, warp-paced (zero block syncs) ----
        #pragma unroll 1
        for (int c = 0; c < NCHUNK; ++c) {
            if (c >= 3) {
                if (!last || c <= 5) CP_WAIT(2);
                else if (c == 6) CP_WAIT(1);
                else CP_WAIT(0);
            }

            if (c <= 4) issue_B(t, c + 3);
            else if (!last) issue_B(t + nCta, c - 5);   // buf (c-5): own reads done at c-1

            const uint32_t* Bsc = Bb + (c & 3) * B_WORDS;
            #pragma unroll
            for (int ks = 0; ks < 2; ++ks) {
                uint32_t a[4][4];
                #pragma unroll
                for (int u = 0; u < 4; ++u) {
                    uint32_t addr = As_u + (uint32_t)((u * 16 + lm_roff) * A_STRIDE
                                                      + c * KCHUNK + ks * 8 + lm_koff) * 4;
                    ldsm_x4(a[u], addr);
                }
                #pragma unroll
                for (int j = 0; j < 4; ++j) {
                    // raw fp32 bits: HW truncates to tf32
                    const uint32_t* bp8 = Bsc + (ks * 8 + lc) * B_STRIDE + nq + j * 8 + lr;
                    uint32_t b0 = bp8[0];
                    uint32_t b1 = bp8[4 * B_STRIDE];
                    #pragma unroll
                    for (int u = 0; u < 4; ++u)
                        mma_tf32(acc[u][j], a[u], b0, b1);
                }
            }
        }

        // ---- A reads done everywhere -> start A(t+1) DMA under the epilogue ----
        __syncthreads();
        if (!last) issue_A(t + nCta);

        // ---- epilogue ----
        float* obase = out + off;
        #pragma unroll
        for (int u = 0; u < 4; ++u) {
            #pragma unroll
            for (int j = 0; j < 4; ++j) {
                int r0 = u * 16 + lr;
                int col = nq + j * 8 + lc * 2;
                float* p0 = obase + (size_t)r0 * vstride + col;
                float* p1 = p0 + 8 * vstride;
                float2 v0 = make_float2(acc[u][j][0], acc[u][j][1]);
                float2 v1 = make_float2(acc[u][j][2], acc[u][j][3]);
                if (term) {
                    red2_f32(p0, v0);            // L2-side add: no return latency
                    red2_f32(p1, v1);
                } else {
                    *(float2*)p0 = v0;           // re-read by term2: keep in L2
                    *(float2*)p1 = v1;
                }
            }
        }
    }
}

extern "C" void kernel_launch(void* const* d_in, const int* in_sizes, int n_in,
                              void* d_out, int out_size)
{
    const float* attn_x = (const float*)d_in[1];
    const float* attn_y = (const float*)d_in[2];
    const float* V      = (const float*)d_in[3];
    const float* sh     = (const float*)d_in[4];
    const float* bi     = (const float*)d_in[5];
    float* out          = (float*)d_out;

    const int B = in_sizes[3] / (128 * 128 * 256);
    const int ntiles = B * 128 * 2;              // half-tiles

    int nsm = 148;
    cudaDeviceGetAttribute(&nsm, cudaDevAttrMultiProcessorCount, 0);
    int grid = 2 * nsm < ntiles ? 2 * nsm : ntiles;

    cudaFuncSetAttribute(gt_mma, cudaFuncAttributeMaxDynamicSharedMemorySize, SMEM_BYTES);

    gt_mma<<<grid, 256, SMEM_BYTES>>>(attn_x, V, sh, bi, out, 0, ntiles);
    gt_mma<<<grid, 256, SMEM_BYTES>>>(attn_y, V, sh, bi, out, 1, ntiles);
}

// round 17
// speedup vs baseline: 1.1260x; 1.1260x over previous
#include <cuda_runtime.h>
#include <cstdint>

#define A_STRIDE 132                     // words
#define B_STRIDE 264                     // words
#define KCHUNK 16
#define NCHUNK 8
#define A_WORDS (64 * A_STRIDE)          // 8448 (64-row half tile)
#define B_WORDS (KCHUNK * B_STRIDE)      // 4224
#define SMEM_BYTES ((A_WORDS + 4 * B_WORDS) * 4)   // 101376 -> 2 CTAs/SM

static __device__ __forceinline__ uint32_t tf32u(float x) {
    uint32_t r;
    asm("cvt.rna.tf32.f32 %0, %1;" : "=r"(r) : "f"(x));
    return r;
}
static __device__ __forceinline__ void cp16(uint32_t dst, const void* src) {
    asm volatile("cp.async.cg.shared.global [%0], [%1], 16;" :: "r"(dst), "l"(src));
}
#define CP_COMMIT() asm volatile("cp.async.commit_group;" ::: "memory")
#define CP_WAIT(n)  asm volatile("cp.async.wait_group %0;" :: "n"(n) : "memory")

// fire-and-forget L2-side float add (no return latency)
static __device__ __forceinline__ void red2_f32(float* p, float2 v) {
    asm volatile("red.global.add.f32 [%0], %1;"   :: "l"(p), "f"(v.x) : "memory");
    asm volatile("red.global.add.f32 [%0+4], %1;" :: "l"(p), "f"(v.y) : "memory");
}
static __device__ __forceinline__ void ldsm_x4(uint32_t r[4], uint32_t addr) {
    asm volatile("ldmatrix.sync.aligned.m8n8.x4.shared.b16 {%0,%1,%2,%3}, [%4];"
                 : "=r"(r[0]), "=r"(r[1]), "=r"(r[2]), "=r"(r[3]) : "r"(addr));
}
static __device__ __forceinline__ void mma_tf32(float c[4], const uint32_t a[4],
                                                uint32_t b0, uint32_t b1) {
    asm volatile(
        "mma.sync.aligned.m16n8k8.row.col.f32.tf32.tf32.f32 "
        "{%0,%1,%2,%3}, {%4,%5,%6,%7}, {%8,%9}, {%0,%1,%2,%3};"
        : "+f"(c[0]), "+f"(c[1]), "+f"(c[2]), "+f"(c[3])
        : "r"(a[0]), "r"(a[1]), "r"(a[2]), "r"(a[3]), "r"(b0), "r"(b1));
}

// ---------------------------------------------------------------------------
// R15 base (best: 187.5us) + hoisted/strength-reduced addressing in the
// chunk loop (alu was 13.8% of peak = ~half of all issue slots).
// Persistent, 256 thr/CTA, 2 CTAs/SM. Half-tile t -> (mhh=(t&1)*64,
// rc=(t>>1)&127, b=t>>8): D[64,256] = softmax(attn[b,rc,mhh..]+g) @ V_t.
// Warp w owns n-cols [w*32, w*32+32): B slab warp-private; zero block syncs
// in chunk loop.  Cross-tile cp.async FIFO:
//   c5/c6/c7 issue B(t+1, 0/1/2); post-chunk sync -> issue A(t+1) -> epilogue
//   head: wait(0); chunks: c<=2 none, c3..c7 wait(2); last tile 2/1/0 tail.
// ---------------------------------------------------------------------------
__global__ void __launch_bounds__(256, 2) gt_mma(
    const float* __restrict__ attn, const float* __restrict__ V,
    const float* __restrict__ sp, const float* __restrict__ bp,
    float* __restrict__ out, int term, int ntiles)
{
    extern __shared__ uint32_t smem[];
    uint32_t* As = smem;                         // [64][132] tf32
    uint32_t* Bb = smem + A_WORDS;               // 4-ring of [16][264] raw fp32
    const uint32_t As_u = (uint32_t)__cvta_generic_to_shared(As);
    const uint32_t Bu   = (uint32_t)__cvta_generic_to_shared(Bb);

    const int tid = threadIdx.x, lane = tid & 31, wid = tid >> 5;
    const int nCta = gridDim.x;
    const float sh = sp[0], bi = bp[0];
    const size_t vstride = term ? (size_t)32768 : (size_t)256;

    const int nq = wid * 32;
    const int lr = lane >> 2, lc = lane & 3;
    const int lm_mat = lane >> 3, lm_row = lane & 7;
    const int lm_roff = (lm_mat & 1) * 8 + lm_row;
    const int lm_koff = (lm_mat >> 1) * 4;

    auto voff_of = [&](int t) -> size_t {
        int rc = (t >> 1) & 127, b = t >> 8;
        return term ? ((size_t)b * 4194304 + (size_t)rc * 256)
                    : (((size_t)b * 128 + rc) * (size_t)32768);
    };
    auto issue_A = [&](int t) {
        int mhh = (t & 1) * 64, rc = (t >> 1) & 127, b = t >> 8;
        const float* src = attn + ((size_t)b * 128 + rc) * (size_t)16384
                         + (size_t)mhh * 128 + (tid >> 5) * 128 + (tid & 31) * 4;
        uint32_t dst = As_u + (uint32_t)(tid >> 5) * (A_STRIDE * 4)
                     + (uint32_t)(tid & 31) * 16;
        #pragma unroll
        for (int q = 0; q < 8; ++q) {
            cp16(dst, src);
            dst += 8 * (A_STRIDE * 4);
            src += 8 * 128;
        }
        CP_COMMIT();
    };
    // warp-private 16k x 32n slab; src = V tile base (precomputed)
    auto issue_B = [&](const float* vb, int chunk) {
        const float* src = vb + (size_t)(chunk * KCHUNK + (lane >> 3)) * vstride
                         + nq + (lane & 7) * 4;
        uint32_t dst = Bu + (uint32_t)(chunk & 3) * (B_WORDS * 4)
                     + (uint32_t)(lane >> 3) * (B_STRIDE * 4)
                     + (uint32_t)nq * 4 + (uint32_t)(lane & 7) * 16;
        #pragma unroll
        for (int q = 0; q < 4; ++q) {
            cp16(dst, src);
            dst += 4 * (B_STRIDE * 4);
            src += 4 * vstride;
        }
        CP_COMMIT();
    };

    int t = blockIdx.x;
    if (t >= ntiles) return;

    const float* vb_cur = V + voff_of(t);
    issue_A(t);
    issue_B(vb_cur, 0); issue_B(vb_cur, 1); issue_B(vb_cur, 2);

    // ldsm base addresses (per-u), bumped by KCHUNK*4 per chunk
    uint32_t a_base0 = As_u + (uint32_t)(lm_roff * A_STRIDE + lm_koff) * 4;

    #pragma unroll 1
    for (; t < ntiles; t += nCta) {
        const bool last = (t + nCta >= ntiles);
        const int mhh = (t & 1) * 64;
        const size_t off = voff_of(t) + (size_t)mhh * vstride;
        const float* vb_next = last ? vb_cur : V + voff_of(t + nCta);

        // ---- head: everything for tile t drained (covered by prev epilogue) ----
        CP_WAIT(0);
        __syncthreads();

        // ---- softmax in place (no max pass; exponents bounded) ----
        float* Af = (float*)As;
        #pragma unroll 2
        for (int rr = 0; rr < 8; ++rr) {
            int row = wid * 8 + rr;
            float4 v = *(const float4*)(Af + row * A_STRIDE + lane * 4);
            float fr = (float)(mhh + row);
            float e[4]; float sum = 0.f;
            #pragma unroll
            for (int j = 0; j < 4; ++j) {
                float d = (float)(lane * 4 + j) - fr;
                float vv = (j == 0 ? v.x : j == 1 ? v.y : j == 2 ? v.z : v.w)
                           - fmaf(sh, d * d, bi);
                e[j] = __expf(vv);
                sum += e[j];
            }
            #pragma unroll
            for (int o = 16; o > 0; o >>= 1) sum += __shfl_xor_sync(~0u, sum, o);
            float inv = 1.0f / sum;
            uint4 w = make_uint4(tf32u(e[0] * inv), tf32u(e[1] * inv),
                                 tf32u(e[2] * inv), tf32u(e[3] * inv));
            *(uint4*)(As + row * A_STRIDE + lane * 4) = w;
        }
        __syncthreads();

        float acc[4][4][4];
        #pragma unroll
        for (int u = 0; u < 4; ++u)
            #pragma unroll
            for (int j = 0; j < 4; ++j)
                #pragma unroll
                for (int q = 0; q < 4; ++q) acc[u][j][q] = 0.f;

        // ---- 8 k-chunks, warp-paced (zero block syncs) ----
        uint32_t a_addr = a_base0;                       // += KCHUNK*4 per chunk
        #pragma unroll 1
        for (int c = 0; c < NCHUNK; ++c) {
            if (c >= 3) {
                if (!last || c <= 5) CP_WAIT(2);
                else if (c == 6) CP_WAIT(1);
                else CP_WAIT(0);
            }

            if (c <= 4) issue_B(vb_cur, c + 3);
            else if (!last) issue_B(vb_next, c - 5);     // buf (c-5): own reads done

            const uint32_t* bpc = Bb + (c & 3) * B_WORDS + lc * B_STRIDE + nq + lr;
            #pragma unroll
            for (int ks = 0; ks < 2; ++ks) {
                uint32_t a[4][4];
                #pragma unroll
                for (int u = 0; u < 4; ++u)
                    ldsm_x4(a[u], a_addr + (uint32_t)(u * 16 * A_STRIDE + ks * 8) * 4);
                const uint32_t* bp8 = bpc + ks * 8 * B_STRIDE;
                #pragma unroll
                for (int j = 0; j < 4; ++j) {
                    // raw fp32 bits: HW truncates to tf32
                    uint32_t b0 = bp8[j * 8];
                    uint32_t b1 = bp8[j * 8 + 4 * B_STRIDE];
                    #pragma unroll
                    for (int u = 0; u < 4; ++u)
                        mma_tf32(acc[u][j], a[u], b0, b1);
                }
            }
            a_addr += KCHUNK * 4;
        }

        // ---- A reads done everywhere -> start A(t+1) DMA under the epilogue ----
        __syncthreads();
        if (!last) issue_A(t + nCta);

        // ---- epilogue ----
        float* obase = out + off + (size_t)lr * vstride + nq + lc * 2;
        #pragma unroll
        for (int u = 0; u < 4; ++u) {
            float* orow = obase + (size_t)(u * 16) * vstride;
            #pragma unroll
            for (int j = 0; j < 4; ++j) {
                float* p0 = orow + j * 8;
                float* p1 = p0 + 8 * vstride;
                float2 v0 = make_float2(acc[u][j][0], acc[u][j][1]);
                float2 v1 = make_float2(acc[u][j][2], acc[u][j][3]);
                if (term) {
                    red2_f32(p0, v0);            // L2-side add: no return latency
                    red2_f32(p1, v1);
                } else {
                    *(float2*)p0 = v0;           // re-read by term2: keep in L2
                    *(float2*)p1 = v1;
                }
            }
        }

        vb_cur = vb_next;
    }
}

extern "C" void kernel_launch(void* const* d_in, const int* in_sizes, int n_in,
                              void* d_out, int out_size)
{
    const float* attn_x = (const float*)d_in[1];
    const float* attn_y = (const float*)d_in[2];
    const float* V      = (const float*)d_in[3];
    const float* sh     = (const float*)d_in[4];
    const float* bi     = (const float*)d_in[5];
    float* out          = (float*)d_out;

    const int B = in_sizes[3] / (128 * 128 * 256);
    const int ntiles = B * 128 * 2;              // half-tiles

    int nsm = 148;
    cudaDeviceGetAttribute(&nsm, cudaDevAttrMultiProcessorCount, 0);
    int grid = 2 * nsm < ntiles ? 2 * nsm : ntiles;

    cudaFuncSetAttribute(gt_mma, cudaFuncAttributeMaxDynamicSharedMemorySize, SMEM_BYTES);

    gt_mma<<<grid, 256, SMEM_BYTES>>>(attn_x, V, sh, bi, out, 0, ntiles);
    gt_mma<<<grid, 256, SMEM_BYTES>>>(attn_y, V, sh, bi, out, 1, ntiles);
}